// round 13
// baseline (speedup 1.0000x reference)
#include <cuda_runtime.h>
#include <cuda_bf16.h>
#include <math.h>
#include <stdint.h>

#define BB 64
#define SS 128
#define HH 1024
#define GG 4096
#define VV 50257
#define VP 50304   // padded vocab rows for guard-free A tiles
#define TT 32
#define NVB 393    // number of logits v-blocks

typedef unsigned long long ull;

// ---------------- scratch (device globals; no allocations) ----------------
__device__ float g_c[BB * HH];
__device__ float g_part[8ull * BB * GG];
__device__ float g_Xg[(size_t)SS * BB * GG];
__device__ int   g_len[BB];
__device__ float g_pv[BB * 512];
__device__ int   g_pi[BB * 512];
// bf16 split pairs
__device__ __nv_bfloat16 g_Whi[(size_t)VP * HH];
__device__ __nv_bfloat16 g_Wlo[(size_t)VP * HH];
__device__ __nv_bfloat16 g_WihHi[(size_t)GG * HH];
__device__ __nv_bfloat16 g_WihLo[(size_t)GG * HH];
__device__ __nv_bfloat16 g_WhhHi[(size_t)GG * HH];
__device__ __nv_bfloat16 g_WhhLo[(size_t)GG * HH];
__device__ __nv_bfloat16 g_hhi[BB * HH];
__device__ __nv_bfloat16 g_hlo[BB * HH];
__device__ __nv_bfloat16 g_xhi[BB * HH];
__device__ __nv_bfloat16 g_xlo[BB * HH];

__device__ __forceinline__ float sigmoidf_(float x) { return 1.0f / (1.0f + expf(-x)); }

// ---------------- mma.sync + cp.async helpers ------------------------------
__device__ __forceinline__ uint32_t smem_u32(const void* p) {
    uint32_t a;
    asm("{ .reg .u64 t; cvta.to.shared.u64 t, %1; cvt.u32.u64 %0, t; }" : "=r"(a) : "l"(p));
    return a;
}
__device__ __forceinline__ void cpasync16(uint32_t saddr, const void* g) {
    asm volatile("cp.async.cg.shared.global [%0], [%1], 16;" :: "r"(saddr), "l"(g));
}
#define CP_COMMIT() asm volatile("cp.async.commit_group;" ::: "memory")
#define CP_WAIT2()  asm volatile("cp.async.wait_group 2;" ::: "memory")
#define CP_WAIT1()  asm volatile("cp.async.wait_group 1;" ::: "memory")
#define CP_WAIT0()  asm volatile("cp.async.wait_group 0;" ::: "memory")

__device__ __forceinline__ void ldmA(uint32_t base, int R0, int kk0, int lane, uint32_t* a) {
    int mat = lane >> 3, ri = lane & 7;
    uint32_t addr = base + (uint32_t)(R0 + ri + ((mat & 1) << 3)) * 80u
                         + (uint32_t)((kk0 + ((mat >> 1) << 3)) << 1);
    asm volatile("ldmatrix.sync.aligned.m8n8.x4.shared.b16 {%0,%1,%2,%3}, [%4];"
        : "=r"(a[0]), "=r"(a[1]), "=r"(a[2]), "=r"(a[3]) : "r"(addr));
}
__device__ __forceinline__ void ldmB(uint32_t base, int N0, int kk0, int lane, uint32_t* b) {
    int mat = lane >> 3, ri = lane & 7;
    uint32_t addr = base + (uint32_t)(N0 + ri + ((mat >> 1) << 3)) * 80u
                         + (uint32_t)((kk0 + ((mat & 1) << 3)) << 1);
    asm volatile("ldmatrix.sync.aligned.m8n8.x4.shared.b16 {%0,%1,%2,%3}, [%4];"
        : "=r"(b[0]), "=r"(b[1]), "=r"(b[2]), "=r"(b[3]) : "r"(addr));
}
__device__ __forceinline__ void mma16816(float* d, const uint32_t* a, const uint32_t* b) {
    asm volatile("mma.sync.aligned.m16n8k16.row.col.f32.bf16.bf16.f32 "
        "{%0,%1,%2,%3}, {%4,%5,%6,%7}, {%8,%9}, {%0,%1,%2,%3};"
        : "+f"(d[0]), "+f"(d[1]), "+f"(d[2]), "+f"(d[3])
        : "r"(a[0]), "r"(a[1]), "r"(a[2]), "r"(a[3]), "r"(b[0]), "r"(b[1]));
}

#define SA_HI 0
#define SA_LO 10240
#define SB_HI 20480
#define SB_LO 25600
#define BUF_BYTES 30720
#define DSMEM   (2 * BUF_BYTES)
#define DSMEM_L (3 * BUF_BYTES)

struct Frag { float acc[2][4][4]; };

__device__ __forceinline__ void load_chunk(char* buf,
    const __nv_bfloat16* Ahi, const __nv_bfloat16* Alo, size_t arow0,
    const __nv_bfloat16* Bhi, const __nv_bfloat16* Blo,
    int k0, int tid)
{
    uint32_t sb = smem_u32(buf);
#pragma unroll
    for (int q0 = 0; q0 < 512; q0 += 256) {
        int q = q0 + tid;
        int r = q >> 2, u = q & 3;
        size_t off = (arow0 + (size_t)r * HH + k0) * 2 + (size_t)u * 16;
        cpasync16(sb + SA_HI + r * 80 + u * 16, (const char*)Ahi + off);
        cpasync16(sb + SA_LO + r * 80 + u * 16, (const char*)Alo + off);
    }
    {
        int r = tid >> 2, u = tid & 3;
        size_t off = ((size_t)r * HH + k0) * 2 + (size_t)u * 16;
        cpasync16(sb + SB_HI + r * 80 + u * 16, (const char*)Bhi + off);
        cpasync16(sb + SB_LO + r * 80 + u * 16, (const char*)Blo + off);
    }
}

__device__ __forceinline__ void compute_chunk(char* buf, int lane, int wm, int wn, Frag& f)
{
    uint32_t sb = smem_u32(buf);
#pragma unroll
    for (int ks = 0; ks < 32; ks += 16) {
        uint32_t ahi[2][4], alo[2][4];
        ldmA(sb + SA_HI, wm * 32,      ks, lane, ahi[0]);
        ldmA(sb + SA_HI, wm * 32 + 16, ks, lane, ahi[1]);
        ldmA(sb + SA_LO, wm * 32,      ks, lane, alo[0]);
        ldmA(sb + SA_LO, wm * 32 + 16, ks, lane, alo[1]);
        uint32_t bhi[8], blo[8];
        ldmB(sb + SB_HI, wn * 32,      ks, lane, bhi);
        ldmB(sb + SB_HI, wn * 32 + 16, ks, lane, bhi + 4);
        ldmB(sb + SB_LO, wn * 32,      ks, lane, blo);
        ldmB(sb + SB_LO, wn * 32 + 16, ks, lane, blo + 4);
#pragma unroll
        for (int i = 0; i < 2; i++)
#pragma unroll
            for (int j = 0; j < 4; j++) {
                mma16816(f.acc[i][j], ahi[i], bhi + j * 2);
                mma16816(f.acc[i][j], ahi[i], blo + j * 2);
                mma16816(f.acc[i][j], alo[i], bhi + j * 2);
            }
    }
}

// 2-stage pipeline (gates/embed)
__device__ __forceinline__ void gemm_pipeline(char* dynbuf,
    const __nv_bfloat16* Ahi, const __nv_bfloat16* Alo, size_t arow0,
    const __nv_bfloat16* Bhi, const __nv_bfloat16* Blo,
    int kbase, int nch, int tid, int lane, int wm, int wn, Frag& f)
{
#pragma unroll
    for (int i = 0; i < 2; i++)
#pragma unroll
        for (int j = 0; j < 4; j++)
#pragma unroll
            for (int q = 0; q < 4; q++) f.acc[i][j][q] = 0.0f;

    char* bufs[2] = { dynbuf, dynbuf + BUF_BYTES };
    load_chunk(bufs[0], Ahi, Alo, arow0, Bhi, Blo, kbase, tid);
    CP_COMMIT();
    for (int ch = 0; ch < nch; ch++) {
        if (ch + 1 < nch) {
            load_chunk(bufs[(ch + 1) & 1], Ahi, Alo, arow0, Bhi, Blo,
                       kbase + (ch + 1) * 32, tid);
            CP_COMMIT();
            CP_WAIT1();
        } else {
            CP_WAIT0();
        }
        __syncthreads();
        compute_chunk(bufs[ch & 1], lane, wm, wn, f);
        __syncthreads();
    }
}

// 3-stage pipeline (logits)
__device__ __forceinline__ void gemm_pipeline3(char* dynbuf,
    const __nv_bfloat16* Ahi, const __nv_bfloat16* Alo, size_t arow0,
    const __nv_bfloat16* Bhi, const __nv_bfloat16* Blo,
    int nch, int tid, int lane, int wm, int wn, Frag& f)
{
#pragma unroll
    for (int i = 0; i < 2; i++)
#pragma unroll
        for (int j = 0; j < 4; j++)
#pragma unroll
            for (int q = 0; q < 4; q++) f.acc[i][j][q] = 0.0f;

    char* bufs[3] = { dynbuf, dynbuf + BUF_BYTES, dynbuf + 2 * BUF_BYTES };
    load_chunk(bufs[0], Ahi, Alo, arow0, Bhi, Blo, 0, tid);
    CP_COMMIT();
    load_chunk(bufs[1], Ahi, Alo, arow0, Bhi, Blo, 32, tid);
    CP_COMMIT();
    int put = 2;
    for (int ch = 0; ch < nch; ch++) {
        if (ch + 2 < nch) {
            load_chunk(bufs[put], Ahi, Alo, arow0, Bhi, Blo, (ch + 2) * 32, tid);
            CP_COMMIT();
            CP_WAIT2();
            put = (put == 2) ? 0 : put + 1;
        } else if (ch + 1 < nch) {
            CP_WAIT1();
        } else {
            CP_WAIT0();
        }
        __syncthreads();
        compute_chunk(bufs[ch % 3], lane, wm, wn, f);
        __syncthreads();
    }
}

template <typename StoreFn>
__device__ __forceinline__ void epilogue(char* dynbuf, int wid, int lane, Frag& f, StoreFn store)
{
    float* F = (float*)dynbuf;
    for (int phase = 0; phase < 2; phase++) {
        __syncthreads();
        if ((wid >> 2) == phase) {
            float* R = F + (wid & 3) * (32 * 33);
            int row = lane >> 2, cp = (lane & 3) * 2;
#pragma unroll
            for (int i = 0; i < 2; i++)
#pragma unroll
                for (int j = 0; j < 4; j++) {
                    R[(j * 8 + cp)     * 33 + i * 16 + row]     = f.acc[i][j][0];
                    R[(j * 8 + cp + 1) * 33 + i * 16 + row]     = f.acc[i][j][1];
                    R[(j * 8 + cp)     * 33 + i * 16 + row + 8] = f.acc[i][j][2];
                    R[(j * 8 + cp + 1) * 33 + i * 16 + row + 8] = f.acc[i][j][3];
                }
            __syncwarp();
            store(R);
        }
    }
}

// ---------------- tiny prep kernels ----------------
__global__ void k_len(const int* __restrict__ ids) {
    __shared__ int cnt[4];
    int b = blockIdx.x;
    int nz = (ids[b * SS + threadIdx.x] != 0) ? 1 : 0;
    unsigned m = __ballot_sync(0xffffffffu, nz);
    if ((threadIdx.x & 31) == 0) cnt[threadIdx.x >> 5] = __popc(m);
    __syncthreads();
    if (threadIdx.x == 0) g_len[b] = cnt[0] + cnt[1] + cnt[2] + cnt[3];
}

__global__ void k_zero() {
    int i = blockIdx.x * 256 + threadIdx.x;
    g_c[i] = 0.0f;
    g_hhi[i] = __float2bfloat16(0.0f);
    g_hlo[i] = __float2bfloat16(0.0f);
}

__global__ void k_split(int sel, const float* __restrict__ src) {
    size_t n, nsrc;
    __nv_bfloat16 *hi, *lo;
    if (sel == 0)      { hi = g_Whi;   lo = g_Wlo;   n = (size_t)VP * HH; nsrc = (size_t)VV * HH; }
    else if (sel == 2) { hi = g_WihHi; lo = g_WihLo; n = (size_t)GG * HH; nsrc = n; }
    else               { hi = g_WhhHi; lo = g_WhhLo; n = (size_t)GG * HH; nsrc = n; }
    for (size_t i = (size_t)blockIdx.x * blockDim.x + threadIdx.x; i < n;
         i += (size_t)gridDim.x * blockDim.x) {
        float w = (i < nsrc) ? src[i] : 0.0f;
        __nv_bfloat16 h = __float2bfloat16(w);
        hi[i] = h;
        lo[i] = __float2bfloat16(w - __bfloat162float(h));
    }
}

// ---------------- HMMA embed (B = fp32 emb rows, split inline) -------------
__global__ __launch_bounds__(256) void k_embed_hmma(
    const int* __restrict__ ids, const float* __restrict__ emb,
    const float* __restrict__ b_ih, const float* __restrict__ b_hh)
{
    extern __shared__ char dynbuf[];
    __shared__ int toks[64];
    const int tid = threadIdx.x;
    const int wid = tid >> 5;
    const int lane = tid & 31;
    const int wm = wid & 3, wn = wid >> 2;
    const int j0 = blockIdx.x * 128;
    const int n0 = blockIdx.y * 64;

    if (tid < 64) {
        int m = n0 + tid;
        toks[tid] = ids[(m & 63) * SS + (m >> 6)];
    }
    __syncthreads();

    Frag f;
#pragma unroll
    for (int i = 0; i < 2; i++)
#pragma unroll
        for (int j = 0; j < 4; j++)
#pragma unroll
            for (int q = 0; q < 4; q++) f.acc[i][j][q] = 0.0f;

    char* bufs[2] = { dynbuf, dynbuf + BUF_BYTES };

    auto loadA = [&](char* buf, int k0) {
        uint32_t sb = smem_u32(buf);
#pragma unroll
        for (int q0 = 0; q0 < 512; q0 += 256) {
            int q = q0 + tid;
            int r = q >> 2, u = q & 3;
            size_t off = ((size_t)(j0 + r) * HH + k0) * 2 + (size_t)u * 16;
            cpasync16(sb + SA_HI + r * 80 + u * 16, (const char*)g_WihHi + off);
            cpasync16(sb + SA_LO + r * 80 + u * 16, (const char*)g_WihLo + off);
        }
    };
    auto loadB = [&](char* buf, int k0) {
        int r = tid >> 2, u = tid & 3;
        const float* src = emb + (size_t)toks[r] * HH + k0 + u * 8;
        float4 a = *(const float4*)src;
        float4 b = *(const float4*)(src + 4);
        float vals[8] = {a.x, a.y, a.z, a.w, b.x, b.y, b.z, b.w};
        uint32_t wh[4], wl[4];
#pragma unroll
        for (int i = 0; i < 4; i++) {
            __nv_bfloat16 h0 = __float2bfloat16(vals[2 * i]);
            __nv_bfloat16 h1 = __float2bfloat16(vals[2 * i + 1]);
            __nv_bfloat162 ph; ph.x = h0; ph.y = h1;
            wh[i] = *(uint32_t*)&ph;
            __nv_bfloat162 pl;
            pl.x = __float2bfloat16(vals[2 * i]     - __bfloat162float(h0));
            pl.y = __float2bfloat16(vals[2 * i + 1] - __bfloat162float(h1));
            wl[i] = *(uint32_t*)&pl;
        }
        *(uint4*)(buf + SB_HI + r * 80 + u * 16) = make_uint4(wh[0], wh[1], wh[2], wh[3]);
        *(uint4*)(buf + SB_LO + r * 80 + u * 16) = make_uint4(wl[0], wl[1], wl[2], wl[3]);
    };

    loadA(bufs[0], 0);
    CP_COMMIT();
    loadB(bufs[0], 0);
    for (int ch = 0; ch < 32; ch++) {
        if (ch + 1 < 32) {
            loadA(bufs[(ch + 1) & 1], (ch + 1) * 32);
            CP_COMMIT();
            loadB(bufs[(ch + 1) & 1], (ch + 1) * 32);
            CP_WAIT1();
        } else {
            CP_WAIT0();
        }
        __syncthreads();
        compute_chunk(bufs[ch & 1], lane, wm, wn, f);
        __syncthreads();
    }

    epilogue(dynbuf, wid, lane, f, [&](float* R) {
        int j = j0 + wm * 32 + lane;
        float bias = b_ih[j] + b_hh[j];
#pragma unroll 8
        for (int bb = 0; bb < 32; bb++) {
            int m = n0 + wn * 32 + bb;
            g_Xg[(size_t)m * GG + j] = R[bb * 33 + lane] + bias;
        }
    });
}

// ---------------- HMMA gates -----------------------------------------------
// mode 0 (prompt): grid (32, 4): W_hh x h -> parts 0..3
// mode 1 (decode): grid (32, 8): y<4: W_ih x x (K=256) -> 0..3; y>=4: W_hh x h -> 4..7
__global__ __launch_bounds__(256) void k_gates_hmma(int mode)
{
    extern __shared__ char dynbuf[];
    const int tid = threadIdx.x;
    const int wid = tid >> 5;
    const int lane = tid & 31;
    const int wm = wid & 3, wn = wid >> 2;
    const int j0 = blockIdx.x * 128;
    const __nv_bfloat16 *Ahi, *Alo, *Bhi, *Blo;
    if (mode == 0 || blockIdx.y >= 4) { Ahi = g_WhhHi; Alo = g_WhhLo; Bhi = g_hhi; Blo = g_hlo; }
    else                              { Ahi = g_WihHi; Alo = g_WihLo; Bhi = g_xhi; Blo = g_xlo; }
    const int part = blockIdx.y;
    const int kbase = (blockIdx.y & 3) * 256;
    float* out = g_part + (size_t)part * (BB * GG);

    Frag f;
    gemm_pipeline(dynbuf, Ahi, Alo, (size_t)j0 * HH,
                  Bhi, Blo, kbase, 8, tid, lane, wm, wn, f);

    epilogue(dynbuf, wid, lane, f, [&](float* R) {
        int j = j0 + wm * 32 + lane;
#pragma unroll 8
        for (int bb = 0; bb < 32; bb++) {
            int b = wn * 32 + bb;
            out[(size_t)b * GG + j] = R[bb * 33 + lane];
        }
    });
}

// ---------------- gate combine + state update ------------------------------
__global__ void k_update(int s, int nparts,
                         const float* __restrict__ bi, const float* __restrict__ bh)
{
    int idx = blockIdx.x * blockDim.x + threadIdx.x;
    int b = idx >> 10;
    int hc = idx & 1023;
    bool valid = (s < 0) || (s < g_len[b]);
    if (!valid) return;
    const float* xadd = (s >= 0) ? (g_Xg + (size_t)s * BB * GG) : nullptr;

    float g4[4];
#pragma unroll
    for (int gi = 0; gi < 4; gi++) {
        int j = gi * HH + hc;
        float v = xadd ? xadd[(size_t)b * GG + j] : (bi[j] + bh[j]);
#pragma unroll
        for (int p = 0; p < 8; p++)
            if (p < nparts) v += g_part[(size_t)p * BB * GG + (size_t)b * GG + j];
        g4[gi] = v;
    }
    float ig = sigmoidf_(g4[0]);
    float fg = sigmoidf_(g4[1]);
    float gg = tanhf(g4[2]);
    float og = sigmoidf_(g4[3]);
    float cn = fg * g_c[idx] + ig * gg;
    float hn = og * tanhf(cn);
    g_c[idx] = cn;
    __nv_bfloat16 hi = __float2bfloat16(hn);
    g_hhi[idx] = hi;
    g_hlo[idx] = __float2bfloat16(hn - __bfloat162float(hi));
}

// ---------------- HMMA logits with fused per-block argmax ------------------
__global__ __launch_bounds__(256) void k_logits_mma(
    const float* __restrict__ b_fc, float* __restrict__ outbuf, int t)
{
    extern __shared__ char dynbuf[];
    const int tid = threadIdx.x;
    const int wid = tid >> 5;
    const int lane = tid & 31;
    const int wm = wid & 3, wn = wid >> 2;
    const int v0 = blockIdx.x * 128;

    Frag f;
    gemm_pipeline3(dynbuf, g_Whi, g_Wlo, (size_t)v0 * HH,
                   g_hhi, g_hlo, 32, tid, lane, wm, wn, f);

    float* F = (float*)dynbuf;
    for (int phase = 0; phase < 2; phase++) {
        __syncthreads();
        if (wn == phase) {
            float* R = F + wm * (32 * 33);
            int row = lane >> 2, cp = (lane & 3) * 2;
#pragma unroll
            for (int i = 0; i < 2; i++)
#pragma unroll
                for (int j = 0; j < 4; j++) {
                    R[(j * 8 + cp)     * 33 + i * 16 + row]     = f.acc[i][j][0];
                    R[(j * 8 + cp + 1) * 33 + i * 16 + row]     = f.acc[i][j][1];
                    R[(j * 8 + cp)     * 33 + i * 16 + row + 8] = f.acc[i][j][2];
                    R[(j * 8 + cp + 1) * 33 + i * 16 + row + 8] = f.acc[i][j][3];
                }
            __syncwarp();
            int v = v0 + wm * 32 + lane;
            if (v < VV) {
                float bias = b_fc[v];
#pragma unroll 8
                for (int bb = 0; bb < 32; bb++) {
                    int b = wn * 32 + bb;
                    outbuf[((size_t)b * TT + t) * VV + v] = R[bb * 33 + lane] + bias;
                }
            }
        }
        __syncthreads();
        // fused per-block argmax for this b-half (all 256 threads)
        int b_local = tid >> 3;   // 0..31
        int vg = tid & 7;         // 0..7, 16 v's each
        float best = -3.4e38f; int bidx = 0x7fffffff;
#pragma unroll 4
        for (int q = 0; q < 16; q++) {
            int vl = vg * 16 + q;
            int v = v0 + vl;
            if (v < VV) {
                float val = F[(vl >> 5) * (32 * 33) + b_local * 33 + (vl & 31)] + b_fc[v];
                if (val > best) { best = val; bidx = v; }
            }
        }
#pragma unroll
        for (int d = 1; d < 8; d <<= 1) {
            float ov = __shfl_xor_sync(0xffffffffu, best, d);
            int   oi = __shfl_xor_sync(0xffffffffu, bidx, d);
            if (ov > best || (ov == best && oi < bidx)) { best = ov; bidx = oi; }
        }
        if (vg == 0) {
            int b = phase * 32 + b_local;
            g_pv[b * 512 + blockIdx.x] = best;
            g_pi[b * 512 + blockIdx.x] = bidx;
        }
    }
}

// ---------------- final argmax over 393 block candidates -------------------
__global__ void k_argmax_fin(const float* __restrict__ emb) {
    __shared__ float sv[256];
    __shared__ int   si[256];
    __shared__ int   stok;
    int b = blockIdx.x;
    float best = -3.4e38f; int bidx = 0x7fffffff;
    for (int blk = threadIdx.x; blk < NVB; blk += 256) {
        float v = g_pv[b * 512 + blk];
        int   i = g_pi[b * 512 + blk];
        if (v > best || (v == best && i < bidx)) { best = v; bidx = i; }
    }
    sv[threadIdx.x] = best; si[threadIdx.x] = bidx;
    __syncthreads();
    for (int st = 128; st > 0; st >>= 1) {
        if (threadIdx.x < st) {
            float o = sv[threadIdx.x + st]; int oi = si[threadIdx.x + st];
            if (o > sv[threadIdx.x] || (o == sv[threadIdx.x] && oi < si[threadIdx.x])) {
                sv[threadIdx.x] = o; si[threadIdx.x] = oi;
            }
        }
        __syncthreads();
    }
    if (threadIdx.x == 0) stok = si[0];
    __syncthreads();
    size_t tok = (size_t)stok;
    float4 v = ((const float4*)(emb + tok * HH))[threadIdx.x];
    float vals[4] = {v.x, v.y, v.z, v.w};
    uint32_t wh[2], wl[2];
#pragma unroll
    for (int i = 0; i < 2; i++) {
        __nv_bfloat16 h0 = __float2bfloat16(vals[2 * i]);
        __nv_bfloat16 h1 = __float2bfloat16(vals[2 * i + 1]);
        __nv_bfloat162 ph; ph.x = h0; ph.y = h1;
        wh[i] = *(uint32_t*)&ph;
        __nv_bfloat162 pl;
        pl.x = __float2bfloat16(vals[2 * i]     - __bfloat162float(h0));
        pl.y = __float2bfloat16(vals[2 * i + 1] - __bfloat162float(h1));
        wl[i] = *(uint32_t*)&pl;
    }
    ((uint2*)(g_xhi + (size_t)b * HH))[threadIdx.x] = make_uint2(wh[0], wh[1]);
    ((uint2*)(g_xlo + (size_t)b * HH))[threadIdx.x] = make_uint2(wl[0], wl[1]);
}

// ---------------- driver ----------------
extern "C" void kernel_launch(void* const* d_in, const int* in_sizes, int n_in,
                              void* d_out, int out_size)
{
    const int*   ids  = (const int*)d_in[0];
    const float* emb  = (const float*)d_in[2];
    const float* W_ih = (const float*)d_in[3];
    const float* W_hh = (const float*)d_in[4];
    const float* b_ih = (const float*)d_in[5];
    const float* b_hh = (const float*)d_in[6];
    const float* W_fc = (const float*)d_in[7];
    const float* b_fc = (const float*)d_in[8];
    float* out = (float*)d_out;

    static cudaStream_t s2 = nullptr;
    static cudaEvent_t evF = nullptr, evJ = nullptr;
    static bool init_done = false;
    if (!init_done) {
        cudaFuncSetAttribute(k_embed_hmma, cudaFuncAttributeMaxDynamicSharedMemorySize, DSMEM);
        cudaFuncSetAttribute(k_gates_hmma, cudaFuncAttributeMaxDynamicSharedMemorySize, DSMEM);
        cudaFuncSetAttribute(k_logits_mma, cudaFuncAttributeMaxDynamicSharedMemorySize, DSMEM_L);
        cudaStreamCreateWithFlags(&s2, cudaStreamNonBlocking);
        cudaEventCreateWithFlags(&evF, cudaEventDisableTiming);
        cudaEventCreateWithFlags(&evJ, cudaEventDisableTiming);
        init_done = true;
    }

    k_zero<<<(BB * HH) / 256, 256>>>();
    k_split<<<512, 256>>>(2, W_ih);
    k_split<<<512, 256>>>(3, W_hh);
    k_len<<<BB, 128>>>(ids);
    k_embed_hmma<<<dim3(GG / 128, (BB * SS) / 64), 256, DSMEM>>>(ids, emb, b_ih, b_hh);
    k_gates_hmma<<<dim3(32, 4), 256, DSMEM>>>(0);
    // fork: W_fc split overlaps with the prompt recurrence
    cudaEventRecord(evF, 0);
    cudaStreamWaitEvent(s2, evF, 0);
    k_split<<<2048, 256, 0, s2>>>(0, W_fc);
    cudaEventRecord(evJ, s2);

    k_update<<<(BB * HH) / 256, 256>>>(0, 4, b_ih, b_hh);
    for (int s = 1; s < SS; s++) {
        k_gates_hmma<<<dim3(32, 4), 256, DSMEM>>>(0);
        k_update<<<(BB * HH) / 256, 256>>>(s, 4, b_ih, b_hh);
    }

    cudaStreamWaitEvent(0, evJ, 0);
    k_logits_mma<<<NVB, 256, DSMEM_L>>>(b_fc, out, 0);

    for (int t = 1; t < TT; t++) {
        k_argmax_fin<<<BB, 256>>>(emb);
        k_gates_hmma<<<dim3(32, 8), 256, DSMEM>>>(1);
        k_update<<<(BB * HH) / 256, 256>>>(-1, 8, b_ih, b_hh);
        k_logits_mma<<<NVB, 256, DSMEM_L>>>(b_fc, out, t);
    }
}

// round 14
// speedup vs baseline: 1.0634x; 1.0634x over previous
#include <cuda_runtime.h>
#include <cuda_bf16.h>
#include <math.h>
#include <stdint.h>

#define BB 64
#define SS 128
#define HH 1024
#define GG 4096
#define VV 50257
#define VP 50304   // padded vocab rows = 262 * 192
#define TT 32
#define NVB 262    // logits v-blocks (192 rows each)

typedef unsigned long long ull;

// ---------------- scratch (device globals; no allocations) ----------------
__device__ float g_c[BB * HH];
__device__ float g_part[8ull * BB * GG];
__device__ float g_Xg[(size_t)SS * BB * GG];
__device__ int   g_len[BB];
__device__ float g_pv[BB * 512];
__device__ int   g_pi[BB * 512];
// bf16 split pairs
__device__ __nv_bfloat16 g_Whi[(size_t)VP * HH];
__device__ __nv_bfloat16 g_Wlo[(size_t)VP * HH];
__device__ __nv_bfloat16 g_WihHi[(size_t)GG * HH];
__device__ __nv_bfloat16 g_WihLo[(size_t)GG * HH];
__device__ __nv_bfloat16 g_WhhHi[(size_t)GG * HH];
__device__ __nv_bfloat16 g_WhhLo[(size_t)GG * HH];
__device__ __nv_bfloat16 g_hhi[BB * HH];
__device__ __nv_bfloat16 g_hlo[BB * HH];
__device__ __nv_bfloat16 g_xhi[BB * HH];
__device__ __nv_bfloat16 g_xlo[BB * HH];

__device__ __forceinline__ float sigmoidf_(float x) { return 1.0f / (1.0f + expf(-x)); }

// ---------------- mma.sync + cp.async helpers ------------------------------
__device__ __forceinline__ uint32_t smem_u32(const void* p) {
    uint32_t a;
    asm("{ .reg .u64 t; cvta.to.shared.u64 t, %1; cvt.u32.u64 %0, t; }" : "=r"(a) : "l"(p));
    return a;
}
__device__ __forceinline__ void cpasync16(uint32_t saddr, const void* g) {
    asm volatile("cp.async.cg.shared.global [%0], [%1], 16;" :: "r"(saddr), "l"(g));
}
#define CP_COMMIT() asm volatile("cp.async.commit_group;" ::: "memory")
#define CP_WAIT1()  asm volatile("cp.async.wait_group 1;" ::: "memory")
#define CP_WAIT0()  asm volatile("cp.async.wait_group 0;" ::: "memory")

__device__ __forceinline__ void ldmA(uint32_t base, int R0, int kk0, int lane, uint32_t* a) {
    int mat = lane >> 3, ri = lane & 7;
    uint32_t addr = base + (uint32_t)(R0 + ri + ((mat & 1) << 3)) * 80u
                         + (uint32_t)((kk0 + ((mat >> 1) << 3)) << 1);
    asm volatile("ldmatrix.sync.aligned.m8n8.x4.shared.b16 {%0,%1,%2,%3}, [%4];"
        : "=r"(a[0]), "=r"(a[1]), "=r"(a[2]), "=r"(a[3]) : "r"(addr));
}
__device__ __forceinline__ void ldmB(uint32_t base, int N0, int kk0, int lane, uint32_t* b) {
    int mat = lane >> 3, ri = lane & 7;
    uint32_t addr = base + (uint32_t)(N0 + ri + ((mat >> 1) << 3)) * 80u
                         + (uint32_t)((kk0 + ((mat & 1) << 3)) << 1);
    asm volatile("ldmatrix.sync.aligned.m8n8.x4.shared.b16 {%0,%1,%2,%3}, [%4];"
        : "=r"(b[0]), "=r"(b[1]), "=r"(b[2]), "=r"(b[3]) : "r"(addr));
}
__device__ __forceinline__ void mma16816(float* d, const uint32_t* a, const uint32_t* b) {
    asm volatile("mma.sync.aligned.m16n8k16.row.col.f32.bf16.bf16.f32 "
        "{%0,%1,%2,%3}, {%4,%5,%6,%7}, {%8,%9}, {%0,%1,%2,%3};"
        : "+f"(d[0]), "+f"(d[1]), "+f"(d[2]), "+f"(d[3])
        : "r"(a[0]), "r"(a[1]), "r"(a[2]), "r"(a[3]), "r"(b[0]), "r"(b[1]));
}

#define SA_HI 0
#define SA_LO 10240
#define SB_HI 20480
#define SB_LO 25600
#define BUF_BYTES 30720
#define DSMEM   (2 * BUF_BYTES)

// logits (192-row A tile) smem layout
#define L_AHI 0
#define L_ALO 15360
#define L_BHI 30720
#define L_BLO 35840
#define LBUF  40960
#define DSMEM_L (2 * LBUF)

struct Frag  { float acc[2][4][4]; };
struct Frag3 { float acc[3][4][4]; };

__device__ __forceinline__ void load_chunk(char* buf,
    const __nv_bfloat16* Ahi, const __nv_bfloat16* Alo, size_t arow0,
    const __nv_bfloat16* Bhi, const __nv_bfloat16* Blo,
    int k0, int tid)
{
    uint32_t sb = smem_u32(buf);
#pragma unroll
    for (int q0 = 0; q0 < 512; q0 += 256) {
        int q = q0 + tid;
        int r = q >> 2, u = q & 3;
        size_t off = (arow0 + (size_t)r * HH + k0) * 2 + (size_t)u * 16;
        cpasync16(sb + SA_HI + r * 80 + u * 16, (const char*)Ahi + off);
        cpasync16(sb + SA_LO + r * 80 + u * 16, (const char*)Alo + off);
    }
    {
        int r = tid >> 2, u = tid & 3;
        size_t off = ((size_t)r * HH + k0) * 2 + (size_t)u * 16;
        cpasync16(sb + SB_HI + r * 80 + u * 16, (const char*)Bhi + off);
        cpasync16(sb + SB_LO + r * 80 + u * 16, (const char*)Blo + off);
    }
}

__device__ __forceinline__ void compute_chunk(char* buf, int lane, int wm, int wn, Frag& f)
{
    uint32_t sb = smem_u32(buf);
#pragma unroll
    for (int ks = 0; ks < 32; ks += 16) {
        uint32_t ahi[2][4], alo[2][4];
        ldmA(sb + SA_HI, wm * 32,      ks, lane, ahi[0]);
        ldmA(sb + SA_HI, wm * 32 + 16, ks, lane, ahi[1]);
        ldmA(sb + SA_LO, wm * 32,      ks, lane, alo[0]);
        ldmA(sb + SA_LO, wm * 32 + 16, ks, lane, alo[1]);
        uint32_t bhi[8], blo[8];
        ldmB(sb + SB_HI, wn * 32,      ks, lane, bhi);
        ldmB(sb + SB_HI, wn * 32 + 16, ks, lane, bhi + 4);
        ldmB(sb + SB_LO, wn * 32,      ks, lane, blo);
        ldmB(sb + SB_LO, wn * 32 + 16, ks, lane, blo + 4);
#pragma unroll
        for (int i = 0; i < 2; i++)
#pragma unroll
            for (int j = 0; j < 4; j++) {
                mma16816(f.acc[i][j], ahi[i], bhi + j * 2);
                mma16816(f.acc[i][j], ahi[i], blo + j * 2);
                mma16816(f.acc[i][j], alo[i], bhi + j * 2);
            }
    }
}

// 2-stage pipeline (gates/embed)
__device__ __forceinline__ void gemm_pipeline(char* dynbuf,
    const __nv_bfloat16* Ahi, const __nv_bfloat16* Alo, size_t arow0,
    const __nv_bfloat16* Bhi, const __nv_bfloat16* Blo,
    int kbase, int nch, int tid, int lane, int wm, int wn, Frag& f)
{
#pragma unroll
    for (int i = 0; i < 2; i++)
#pragma unroll
        for (int j = 0; j < 4; j++)
#pragma unroll
            for (int q = 0; q < 4; q++) f.acc[i][j][q] = 0.0f;

    char* bufs[2] = { dynbuf, dynbuf + BUF_BYTES };
    load_chunk(bufs[0], Ahi, Alo, arow0, Bhi, Blo, kbase, tid);
    CP_COMMIT();
    for (int ch = 0; ch < nch; ch++) {
        if (ch + 1 < nch) {
            load_chunk(bufs[(ch + 1) & 1], Ahi, Alo, arow0, Bhi, Blo,
                       kbase + (ch + 1) * 32, tid);
            CP_COMMIT();
            CP_WAIT1();
        } else {
            CP_WAIT0();
        }
        __syncthreads();
        compute_chunk(bufs[ch & 1], lane, wm, wn, f);
        __syncthreads();
    }
}

// ---- logits-specific 192-row machinery ----
__device__ __forceinline__ void load_chunkL(char* buf, size_t arow0, int k0, int tid)
{
    uint32_t sb = smem_u32(buf);
#pragma unroll
    for (int q0 = 0; q0 < 768; q0 += 256) {
        int q = q0 + tid;
        int r = q >> 2, u = q & 3;
        size_t off = (arow0 + (size_t)r * HH + k0) * 2 + (size_t)u * 16;
        cpasync16(sb + L_AHI + r * 80 + u * 16, (const char*)g_Whi + off);
        cpasync16(sb + L_ALO + r * 80 + u * 16, (const char*)g_Wlo + off);
    }
    {
        int r = tid >> 2, u = tid & 3;
        size_t off = ((size_t)r * HH + k0) * 2 + (size_t)u * 16;
        cpasync16(sb + L_BHI + r * 80 + u * 16, (const char*)g_hhi + off);
        cpasync16(sb + L_BLO + r * 80 + u * 16, (const char*)g_hlo + off);
    }
}

__device__ __forceinline__ void compute_chunkL(char* buf, int lane, int wm, int wn, Frag3& f)
{
    uint32_t sb = smem_u32(buf);
#pragma unroll
    for (int ks = 0; ks < 32; ks += 16) {
        uint32_t ahi[3][4], alo[3][4];
#pragma unroll
        for (int i = 0; i < 3; i++) {
            ldmA(sb + L_AHI, wm * 48 + i * 16, ks, lane, ahi[i]);
            ldmA(sb + L_ALO, wm * 48 + i * 16, ks, lane, alo[i]);
        }
        uint32_t bhi[8], blo[8];
        ldmB(sb + L_BHI, wn * 32,      ks, lane, bhi);
        ldmB(sb + L_BHI, wn * 32 + 16, ks, lane, bhi + 4);
        ldmB(sb + L_BLO, wn * 32,      ks, lane, blo);
        ldmB(sb + L_BLO, wn * 32 + 16, ks, lane, blo + 4);
#pragma unroll
        for (int i = 0; i < 3; i++)
#pragma unroll
            for (int j = 0; j < 4; j++) {
                mma16816(f.acc[i][j], ahi[i], bhi + j * 2);
                mma16816(f.acc[i][j], ahi[i], blo + j * 2);
                mma16816(f.acc[i][j], alo[i], bhi + j * 2);
            }
    }
}

template <typename StoreFn>
__device__ __forceinline__ void epilogue(char* dynbuf, int wid, int lane, Frag& f, StoreFn store)
{
    float* F = (float*)dynbuf;
    for (int phase = 0; phase < 2; phase++) {
        __syncthreads();
        if ((wid >> 2) == phase) {
            float* R = F + (wid & 3) * (32 * 33);
            int row = lane >> 2, cp = (lane & 3) * 2;
#pragma unroll
            for (int i = 0; i < 2; i++)
#pragma unroll
                for (int j = 0; j < 4; j++) {
                    R[(j * 8 + cp)     * 33 + i * 16 + row]     = f.acc[i][j][0];
                    R[(j * 8 + cp + 1) * 33 + i * 16 + row]     = f.acc[i][j][1];
                    R[(j * 8 + cp)     * 33 + i * 16 + row + 8] = f.acc[i][j][2];
                    R[(j * 8 + cp + 1) * 33 + i * 16 + row + 8] = f.acc[i][j][3];
                }
            __syncwarp();
            store(R);
        }
    }
}

// ---------------- tiny prep kernels ----------------
__global__ void k_len(const int* __restrict__ ids) {
    __shared__ int cnt[4];
    int b = blockIdx.x;
    int nz = (ids[b * SS + threadIdx.x] != 0) ? 1 : 0;
    unsigned m = __ballot_sync(0xffffffffu, nz);
    if ((threadIdx.x & 31) == 0) cnt[threadIdx.x >> 5] = __popc(m);
    __syncthreads();
    if (threadIdx.x == 0) g_len[b] = cnt[0] + cnt[1] + cnt[2] + cnt[3];
}

__global__ void k_zero() {
    int i = blockIdx.x * 256 + threadIdx.x;
    g_c[i] = 0.0f;
    g_hhi[i] = __float2bfloat16(0.0f);
    g_hlo[i] = __float2bfloat16(0.0f);
}

__global__ void k_split(int sel, const float* __restrict__ src) {
    size_t n, nsrc;
    __nv_bfloat16 *hi, *lo;
    if (sel == 0)      { hi = g_Whi;   lo = g_Wlo;   n = (size_t)VP * HH; nsrc = (size_t)VV * HH; }
    else if (sel == 2) { hi = g_WihHi; lo = g_WihLo; n = (size_t)GG * HH; nsrc = n; }
    else               { hi = g_WhhHi; lo = g_WhhLo; n = (size_t)GG * HH; nsrc = n; }
    for (size_t i = (size_t)blockIdx.x * blockDim.x + threadIdx.x; i < n;
         i += (size_t)gridDim.x * blockDim.x) {
        float w = (i < nsrc) ? src[i] : 0.0f;
        __nv_bfloat16 h = __float2bfloat16(w);
        hi[i] = h;
        lo[i] = __float2bfloat16(w - __bfloat162float(h));
    }
}

// ---------------- HMMA embed (B = fp32 emb rows, split inline) -------------
__global__ __launch_bounds__(256) void k_embed_hmma(
    const int* __restrict__ ids, const float* __restrict__ emb,
    const float* __restrict__ b_ih, const float* __restrict__ b_hh)
{
    extern __shared__ char dynbuf[];
    __shared__ int toks[64];
    const int tid = threadIdx.x;
    const int wid = tid >> 5;
    const int lane = tid & 31;
    const int wm = wid & 3, wn = wid >> 2;
    const int j0 = blockIdx.x * 128;
    const int n0 = blockIdx.y * 64;

    if (tid < 64) {
        int m = n0 + tid;
        toks[tid] = ids[(m & 63) * SS + (m >> 6)];
    }
    __syncthreads();

    Frag f;
#pragma unroll
    for (int i = 0; i < 2; i++)
#pragma unroll
        for (int j = 0; j < 4; j++)
#pragma unroll
            for (int q = 0; q < 4; q++) f.acc[i][j][q] = 0.0f;

    char* bufs[2] = { dynbuf, dynbuf + BUF_BYTES };

    auto loadA = [&](char* buf, int k0) {
        uint32_t sb = smem_u32(buf);
#pragma unroll
        for (int q0 = 0; q0 < 512; q0 += 256) {
            int q = q0 + tid;
            int r = q >> 2, u = q & 3;
            size_t off = ((size_t)(j0 + r) * HH + k0) * 2 + (size_t)u * 16;
            cpasync16(sb + SA_HI + r * 80 + u * 16, (const char*)g_WihHi + off);
            cpasync16(sb + SA_LO + r * 80 + u * 16, (const char*)g_WihLo + off);
        }
    };
    auto loadB = [&](char* buf, int k0) {
        int r = tid >> 2, u = tid & 3;
        const float* src = emb + (size_t)toks[r] * HH + k0 + u * 8;
        float4 a = *(const float4*)src;
        float4 b = *(const float4*)(src + 4);
        float vals[8] = {a.x, a.y, a.z, a.w, b.x, b.y, b.z, b.w};
        uint32_t wh[4], wl[4];
#pragma unroll
        for (int i = 0; i < 4; i++) {
            __nv_bfloat16 h0 = __float2bfloat16(vals[2 * i]);
            __nv_bfloat16 h1 = __float2bfloat16(vals[2 * i + 1]);
            __nv_bfloat162 ph; ph.x = h0; ph.y = h1;
            wh[i] = *(uint32_t*)&ph;
            __nv_bfloat162 pl;
            pl.x = __float2bfloat16(vals[2 * i]     - __bfloat162float(h0));
            pl.y = __float2bfloat16(vals[2 * i + 1] - __bfloat162float(h1));
            wl[i] = *(uint32_t*)&pl;
        }
        *(uint4*)(buf + SB_HI + r * 80 + u * 16) = make_uint4(wh[0], wh[1], wh[2], wh[3]);
        *(uint4*)(buf + SB_LO + r * 80 + u * 16) = make_uint4(wl[0], wl[1], wl[2], wl[3]);
    };

    loadA(bufs[0], 0);
    CP_COMMIT();
    loadB(bufs[0], 0);
    for (int ch = 0; ch < 32; ch++) {
        if (ch + 1 < 32) {
            loadA(bufs[(ch + 1) & 1], (ch + 1) * 32);
            CP_COMMIT();
            loadB(bufs[(ch + 1) & 1], (ch + 1) * 32);
            CP_WAIT1();
        } else {
            CP_WAIT0();
        }
        __syncthreads();
        compute_chunk(bufs[ch & 1], lane, wm, wn, f);
        __syncthreads();
    }

    epilogue(dynbuf, wid, lane, f, [&](float* R) {
        int j = j0 + wm * 32 + lane;
        float bias = b_ih[j] + b_hh[j];
#pragma unroll 8
        for (int bb = 0; bb < 32; bb++) {
            int m = n0 + wn * 32 + bb;
            g_Xg[(size_t)m * GG + j] = R[bb * 33 + lane] + bias;
        }
    });
}

// ---------------- HMMA gates -----------------------------------------------
// mode 0 (prompt): grid (32, 4): W_hh x h -> parts 0..3
// mode 1 (decode): grid (32, 8): y<4: W_ih x x (K=256) -> 0..3; y>=4: W_hh x h -> 4..7
__global__ __launch_bounds__(256) void k_gates_hmma(int mode)
{
    extern __shared__ char dynbuf[];
    const int tid = threadIdx.x;
    const int wid = tid >> 5;
    const int lane = tid & 31;
    const int wm = wid & 3, wn = wid >> 2;
    const int j0 = blockIdx.x * 128;
    const __nv_bfloat16 *Ahi, *Alo, *Bhi, *Blo;
    if (mode == 0 || blockIdx.y >= 4) { Ahi = g_WhhHi; Alo = g_WhhLo; Bhi = g_hhi; Blo = g_hlo; }
    else                              { Ahi = g_WihHi; Alo = g_WihLo; Bhi = g_xhi; Blo = g_xlo; }
    const int part = blockIdx.y;
    const int kbase = (blockIdx.y & 3) * 256;
    float* out = g_part + (size_t)part * (BB * GG);

    Frag f;
    gemm_pipeline(dynbuf, Ahi, Alo, (size_t)j0 * HH,
                  Bhi, Blo, kbase, 8, tid, lane, wm, wn, f);

    epilogue(dynbuf, wid, lane, f, [&](float* R) {
        int j = j0 + wm * 32 + lane;
#pragma unroll 8
        for (int bb = 0; bb < 32; bb++) {
            int b = wn * 32 + bb;
            out[(size_t)b * GG + j] = R[bb * 33 + lane];
        }
    });
}

// ---------------- gate combine + state update ------------------------------
__global__ void k_update(int s, int nparts,
                         const float* __restrict__ bi, const float* __restrict__ bh)
{
    int idx = blockIdx.x * blockDim.x + threadIdx.x;
    int b = idx >> 10;
    int hc = idx & 1023;
    bool valid = (s < 0) || (s < g_len[b]);
    if (!valid) return;
    const float* xadd = (s >= 0) ? (g_Xg + (size_t)s * BB * GG) : nullptr;

    float g4[4];
#pragma unroll
    for (int gi = 0; gi < 4; gi++) {
        int j = gi * HH + hc;
        float v = xadd ? xadd[(size_t)b * GG + j] : (bi[j] + bh[j]);
#pragma unroll
        for (int p = 0; p < 8; p++)
            if (p < nparts) v += g_part[(size_t)p * BB * GG + (size_t)b * GG + j];
        g4[gi] = v;
    }
    float ig = sigmoidf_(g4[0]);
    float fg = sigmoidf_(g4[1]);
    float gg = tanhf(g4[2]);
    float og = sigmoidf_(g4[3]);
    float cn = fg * g_c[idx] + ig * gg;
    float hn = og * tanhf(cn);
    g_c[idx] = cn;
    __nv_bfloat16 hi = __float2bfloat16(hn);
    g_hhi[idx] = hi;
    g_hlo[idx] = __float2bfloat16(hn - __bfloat162float(hi));
}

// ---------------- HMMA logits (192-row tile, single wave) ------------------
__global__ __launch_bounds__(256, 2) void k_logits_mma(
    const float* __restrict__ b_fc, float* __restrict__ outbuf, int t)
{
    extern __shared__ char dynbuf[];
    const int tid = threadIdx.x;
    const int wid = tid >> 5;
    const int lane = tid & 31;
    const int wm = wid & 3, wn = wid >> 2;
    const int v0 = blockIdx.x * 192;

    Frag3 f;
#pragma unroll
    for (int i = 0; i < 3; i++)
#pragma unroll
        for (int j = 0; j < 4; j++)
#pragma unroll
            for (int q = 0; q < 4; q++) f.acc[i][j][q] = 0.0f;

    char* bufs[2] = { dynbuf, dynbuf + LBUF };
    load_chunkL(bufs[0], (size_t)v0 * HH, 0, tid);
    CP_COMMIT();
    for (int ch = 0; ch < 32; ch++) {
        if (ch + 1 < 32) {
            load_chunkL(bufs[(ch + 1) & 1], (size_t)v0 * HH, (ch + 1) * 32, tid);
            CP_COMMIT();
            CP_WAIT1();
        } else {
            CP_WAIT0();
        }
        __syncthreads();
        compute_chunkL(bufs[ch & 1], lane, wm, wn, f);
        __syncthreads();
    }

    // epilogue: transpose to smem [n(32)][m(48) pitch 49] per warp, store + argmax
    float* F = (float*)dynbuf;
    for (int phase = 0; phase < 2; phase++) {
        __syncthreads();
        if (wn == phase) {
            float* R = F + wm * (32 * 49);
            int row = lane >> 2, cp = (lane & 3) * 2;
#pragma unroll
            for (int i = 0; i < 3; i++)
#pragma unroll
                for (int j = 0; j < 4; j++) {
                    R[(j * 8 + cp)     * 49 + i * 16 + row]     = f.acc[i][j][0];
                    R[(j * 8 + cp + 1) * 49 + i * 16 + row]     = f.acc[i][j][1];
                    R[(j * 8 + cp)     * 49 + i * 16 + row + 8] = f.acc[i][j][2];
                    R[(j * 8 + cp + 1) * 49 + i * 16 + row + 8] = f.acc[i][j][3];
                }
            __syncwarp();
#pragma unroll
            for (int vloc = 0; vloc < 48; vloc += 32) {
                int vl = vloc + lane;
                if (vl < 48) {
                    int v = v0 + wm * 48 + vl;
                    if (v < VV) {
                        float bias = b_fc[v];
#pragma unroll 8
                        for (int bb = 0; bb < 32; bb++) {
                            int b = wn * 32 + bb;
                            outbuf[((size_t)b * TT + t) * VV + v] = R[bb * 49 + vl] + bias;
                        }
                    }
                }
            }
        }
        __syncthreads();
        // fused per-block argmax for this b-half (all 256 threads, 192 v's)
        int b_local = tid >> 3;   // 0..31
        int vg = tid & 7;         // 0..7, 24 v's each
        float best = -3.4e38f; int bidx = 0x7fffffff;
#pragma unroll 4
        for (int q = 0; q < 24; q++) {
            int vl = vg * 24 + q;
            int v = v0 + vl;
            if (v < VV) {
                float val = F[(vl / 48) * (32 * 49) + b_local * 49 + (vl % 48)] + b_fc[v];
                if (val > best) { best = val; bidx = v; }
            }
        }
#pragma unroll
        for (int d = 1; d < 8; d <<= 1) {
            float ov = __shfl_xor_sync(0xffffffffu, best, d);
            int   oi = __shfl_xor_sync(0xffffffffu, bidx, d);
            if (ov > best || (ov == best && oi < bidx)) { best = ov; bidx = oi; }
        }
        if (vg == 0) {
            int b = phase * 32 + b_local;
            g_pv[b * 512 + blockIdx.x] = best;
            g_pi[b * 512 + blockIdx.x] = bidx;
        }
    }
}

// ---------------- final argmax over 262 block candidates -------------------
__global__ void k_argmax_fin(const float* __restrict__ emb) {
    __shared__ float sv[256];
    __shared__ int   si[256];
    __shared__ int   stok;
    int b = blockIdx.x;
    float best = -3.4e38f; int bidx = 0x7fffffff;
    for (int blk = threadIdx.x; blk < NVB; blk += 256) {
        float v = g_pv[b * 512 + blk];
        int   i = g_pi[b * 512 + blk];
        if (v > best || (v == best && i < bidx)) { best = v; bidx = i; }
    }
    sv[threadIdx.x] = best; si[threadIdx.x] = bidx;
    __syncthreads();
    for (int st = 128; st > 0; st >>= 1) {
        if (threadIdx.x < st) {
            float o = sv[threadIdx.x + st]; int oi = si[threadIdx.x + st];
            if (o > sv[threadIdx.x] || (o == sv[threadIdx.x] && oi < si[threadIdx.x])) {
                sv[threadIdx.x] = o; si[threadIdx.x] = oi;
            }
        }
        __syncthreads();
    }
    if (threadIdx.x == 0) stok = si[0];
    __syncthreads();
    size_t tok = (size_t)stok;
    float4 v = ((const float4*)(emb + tok * HH))[threadIdx.x];
    float vals[4] = {v.x, v.y, v.z, v.w};
    uint32_t wh[2], wl[2];
#pragma unroll
    for (int i = 0; i < 2; i++) {
        __nv_bfloat16 h0 = __float2bfloat16(vals[2 * i]);
        __nv_bfloat16 h1 = __float2bfloat16(vals[2 * i + 1]);
        __nv_bfloat162 ph; ph.x = h0; ph.y = h1;
        wh[i] = *(uint32_t*)&ph;
        __nv_bfloat162 pl;
        pl.x = __float2bfloat16(vals[2 * i]     - __bfloat162float(h0));
        pl.y = __float2bfloat16(vals[2 * i + 1] - __bfloat162float(h1));
        wl[i] = *(uint32_t*)&pl;
    }
    ((uint2*)(g_xhi + (size_t)b * HH))[threadIdx.x] = make_uint2(wh[0], wh[1]);
    ((uint2*)(g_xlo + (size_t)b * HH))[threadIdx.x] = make_uint2(wl[0], wl[1]);
}

// ---------------- driver ----------------
extern "C" void kernel_launch(void* const* d_in, const int* in_sizes, int n_in,
                              void* d_out, int out_size)
{
    const int*   ids  = (const int*)d_in[0];
    const float* emb  = (const float*)d_in[2];
    const float* W_ih = (const float*)d_in[3];
    const float* W_hh = (const float*)d_in[4];
    const float* b_ih = (const float*)d_in[5];
    const float* b_hh = (const float*)d_in[6];
    const float* W_fc = (const float*)d_in[7];
    const float* b_fc = (const float*)d_in[8];
    float* out = (float*)d_out;

    static cudaStream_t s2 = nullptr;
    static cudaEvent_t evF = nullptr, evJ = nullptr;
    static bool init_done = false;
    if (!init_done) {
        cudaFuncSetAttribute(k_embed_hmma, cudaFuncAttributeMaxDynamicSharedMemorySize, DSMEM);
        cudaFuncSetAttribute(k_gates_hmma, cudaFuncAttributeMaxDynamicSharedMemorySize, DSMEM);
        cudaFuncSetAttribute(k_logits_mma, cudaFuncAttributeMaxDynamicSharedMemorySize, DSMEM_L);
        cudaStreamCreateWithFlags(&s2, cudaStreamNonBlocking);
        cudaEventCreateWithFlags(&evF, cudaEventDisableTiming);
        cudaEventCreateWithFlags(&evJ, cudaEventDisableTiming);
        init_done = true;
    }

    k_zero<<<(BB * HH) / 256, 256>>>();
    k_split<<<512, 256>>>(2, W_ih);
    k_split<<<512, 256>>>(3, W_hh);
    k_len<<<BB, 128>>>(ids);
    k_embed_hmma<<<dim3(GG / 128, (BB * SS) / 64), 256, DSMEM>>>(ids, emb, b_ih, b_hh);
    k_gates_hmma<<<dim3(32, 4), 256, DSMEM>>>(0);
    // fork: W_fc split overlaps with the prompt recurrence
    cudaEventRecord(evF, 0);
    cudaStreamWaitEvent(s2, evF, 0);
    k_split<<<2048, 256, 0, s2>>>(0, W_fc);
    cudaEventRecord(evJ, s2);

    k_update<<<(BB * HH) / 256, 256>>>(0, 4, b_ih, b_hh);
    for (int s = 1; s < SS; s++) {
        k_gates_hmma<<<dim3(32, 4), 256, DSMEM>>>(0);
        k_update<<<(BB * HH) / 256, 256>>>(s, 4, b_ih, b_hh);
    }

    cudaStreamWaitEvent(0, evJ, 0);
    k_logits_mma<<<NVB, 256, DSMEM_L>>>(b_fc, out, 0);

    for (int t = 1; t < TT; t++) {
        k_argmax_fin<<<BB, 256>>>(emb);
        k_gates_hmma<<<dim3(32, 8), 256, DSMEM>>>(1);
        k_update<<<(BB * HH) / 256, 256>>>(-1, 8, b_ih, b_hh);
        k_logits_mma<<<NVB, 256, DSMEM_L>>>(b_fc, out, t);
    }
}